// round 6
// baseline (speedup 1.0000x reference)
#include <cuda_runtime.h>
#include <cuda_bf16.h>
#include <math.h>
#include <stdint.h>

// ---------------------------------------------------------------------------
// Problem constants (fixed instance)
// ---------------------------------------------------------------------------
#define N_P    16384
#define NKERN  64
#define MAXE   3000000
#define MAXBE  1000000
#define RADIUS_F 0.1125f
#define INV_R   (1.0f / RADIUS_F)
#define DT_F    0.02f
#define INV_DT  50.0f
#define GRAV_Y  (-9.81f)
#define FOUR_OVER_PI_F 1.2732395447351628f

// ---------------------------------------------------------------------------
// Static device scratch
// ---------------------------------------------------------------------------
__device__ __align__(256) __nv_bfloat16 g_Ahi[(size_t)N_P * 6144];
__device__ __align__(256) __nv_bfloat16 g_Alo[(size_t)N_P * 6144];
// packed split weights (transposed to [Cout, K]): Wc1 | Wc2 | W0f | W0o
#define OFF_WC1 0
#define OFF_WC2 393216
#define OFF_W0F 655360
#define OFF_W0O 663552
#define W_TOTAL 669696
__device__ __align__(256) __nv_bfloat16 g_Wh[W_TOTAL];
__device__ __align__(256) __nv_bfloat16 g_Wl[W_TOTAL];

__device__ float g_w8[(size_t)MAXE * 8];
__device__ int   g_base[MAXE];
__device__ float g_w8b[(size_t)MAXBE * 8];
__device__ int   g_baseb[MAXBE];
__device__ int   g_rs_ff[N_P + 1];
__device__ int   g_rs_bf[N_P + 1];
__device__ float g_pos2[N_P * 3];
__device__ float g_feats[N_P * 4];
__device__ float g_h96[N_P * 96];
__device__ float g_h1[N_P * 64];
__device__ float g_h2[N_P * 64];
__device__ float g_x64[N_P * 64];
__device__ float g_h3[N_P * 3];

// ---------------------------------------------------------------------------
// PTX helpers (cp.async / ldmatrix / mma.sync — all valid on compute_103)
// ---------------------------------------------------------------------------
__device__ __forceinline__ uint32_t smem_u32(const void* p) {
    uint32_t a;
    asm("{ .reg .u64 t; cvta.to.shared.u64 t, %1; cvt.u32.u64 %0, t; }" : "=r"(a) : "l"(p));
    return a;
}

__device__ __forceinline__ void cp16(uint32_t dst, const void* src) {
    asm volatile("cp.async.cg.shared.global [%0], [%1], 16;" :: "r"(dst), "l"(src));
}
__device__ __forceinline__ void cp_commit() { asm volatile("cp.async.commit_group;"); }
template <int N>
__device__ __forceinline__ void cp_wait() { asm volatile("cp.async.wait_group %0;" :: "n"(N)); }

__device__ __forceinline__ void ldm_x4(uint32_t* r, uint32_t addr) {
    asm volatile("ldmatrix.sync.aligned.m8n8.x4.shared.b16 {%0,%1,%2,%3}, [%4];"
                 : "=r"(r[0]), "=r"(r[1]), "=r"(r[2]), "=r"(r[3]) : "r"(addr));
}

__device__ __forceinline__ void mma_bf16(float* d, const uint32_t* a, uint32_t b0, uint32_t b1) {
    asm volatile(
        "mma.sync.aligned.m16n8k16.row.col.f32.bf16.bf16.f32 "
        "{%0,%1,%2,%3}, {%4,%5,%6,%7}, {%8,%9}, {%0,%1,%2,%3};"
        : "+f"(d[0]), "+f"(d[1]), "+f"(d[2]), "+f"(d[3])
        : "r"(a[0]), "r"(a[1]), "r"(a[2]), "r"(a[3]), "r"(b0), "r"(b1));
}

__device__ __forceinline__ uint32_t sw128(uint32_t off) {
    return off ^ ((off >> 3) & 0x70u);
}

// ---------------------------------------------------------------------------
// Geometry (mirrors JAX reference)
// ---------------------------------------------------------------------------
__device__ __forceinline__ float signf(float x) {
    return (x > 0.f) ? 1.f : ((x < 0.f) ? -1.f : 0.f);
}

__device__ __forceinline__ void edge_geom(float x, float y, float z,
                                          float* __restrict__ w8, int* __restrict__ basep)
{
    float r2 = x * x + y * y + z * z;
    float win = 1.f - r2;
    win = win * win * win;
    win = fminf(fmaxf(win, 0.f), 1.f);

    float norm = sqrtf(r2 + 1e-24f);
    float xy_sq = x * x + y * y;
    bool zero = r2 < 1e-12f;
    bool cone = 1.25f * z * z > xy_sq;
    float s_cone = sqrtf(3.f * norm / (norm + fabsf(z) + 1e-12f));
    float s_side = norm / sqrtf(xy_sq + 1e-24f);
    float xc = zero ? 0.f : (cone ? x * s_cone : x * s_side);
    float yc = zero ? 0.f : (cone ? y * s_cone : y * s_side);
    float zc = zero ? 0.f : (cone ? signf(z) * norm : 1.5f * z);

    float nxy_sq = xc * xc + yc * yc;
    float nxy = sqrtf(nxy_sq + 1e-24f);
    bool zero_xy = nxy_sq < 1e-12f;
    bool xbig = fabsf(xc) > fabsf(yc);
    float dx_ = (fabsf(xc) > 1e-12f) ? xc : 1.f;
    float dy_ = (fabsf(yc) > 1e-12f) ? yc : 1.f;
    float tx = signf(xc) * nxy;
    float ty = signf(yc) * nxy;
    float xq = zero_xy ? 0.f : (xbig ? tx : ty * FOUR_OVER_PI_F * atanf(xc / dy_));
    float yq = zero_xy ? 0.f : (xbig ? tx * FOUR_OVER_PI_F * atanf(yc / dx_) : ty);

    float gx = (xq + 1.f) * 1.5f;
    float gy = (yq + 1.f) * 1.5f;
    float gz = (zc + 1.f) * 1.5f;
    float g0x = fminf(fmaxf(floorf(gx), 0.f), 2.f);
    float g0y = fminf(fmaxf(floorf(gy), 0.f), 2.f);
    float g0z = fminf(fmaxf(floorf(gz), 0.f), 2.f);
    float fx = gx - g0x, fy = gy - g0y, fz = gz - g0z;
    int base = (int)g0z * 16 + (int)g0y * 4 + (int)g0x;
    float ax = 1.f - fx, ay = 1.f - fy, az = 1.f - fz;

    w8[0] = az * ay * ax * win;
    w8[1] = az * ay * fx * win;
    w8[2] = az * fy * ax * win;
    w8[3] = az * fy * fx * win;
    w8[4] = fz * ay * ax * win;
    w8[5] = fz * ay * fx * win;
    w8[6] = fz * fy * ax * win;
    w8[7] = fz * fy * fx * win;
    *basep = base;
}

__constant__ int c_offs[8] = {0, 1, 4, 5, 16, 17, 20, 21};

// ---------------------------------------------------------------------------
// Small kernels
// ---------------------------------------------------------------------------
__global__ void prep_kernel(const float* __restrict__ pos, const float* __restrict__ vel, int n)
{
    int i = blockIdx.x * blockDim.x + threadIdx.x;
    if (i >= n) return;
    float vx = vel[i * 3 + 0], vy = vel[i * 3 + 1], vz = vel[i * 3 + 2];
    float v2x = vx, v2y = vy + DT_F * GRAV_Y, v2z = vz;
    g_pos2[i * 3 + 0] = pos[i * 3 + 0] + DT_F * 0.5f * (v2x + vx);
    g_pos2[i * 3 + 1] = pos[i * 3 + 1] + DT_F * 0.5f * (v2y + vy);
    g_pos2[i * 3 + 2] = pos[i * 3 + 2] + DT_F * 0.5f * (v2z + vz);
    g_feats[i * 4 + 0] = 1.f;
    g_feats[i * 4 + 1] = v2x;
    g_feats[i * 4 + 2] = v2y;
    g_feats[i * 4 + 3] = v2z;
}

__global__ void fill_int_kernel(int* __restrict__ p, int v, int cnt)
{
    int i = blockIdx.x * blockDim.x + threadIdx.x;
    if (i < cnt) p[i] = v;
}

__global__ void rowstart_kernel(const int* __restrict__ dst, int E, int* __restrict__ rs)
{
    int e = blockIdx.x * blockDim.x + threadIdx.x;
    if (e >= E) return;
    int d = dst[e];
    int p = (e == 0) ? -1 : dst[e - 1];
    for (int dd = p + 1; dd <= d; dd++) rs[dd] = e;
}

__global__ void geom_kernel(const float* __restrict__ sp, const float* __restrict__ dp,
                            const int* __restrict__ src, const int* __restrict__ dst, int E,
                            float* __restrict__ w8, int* __restrict__ base)
{
    int e = blockIdx.x * blockDim.x + threadIdx.x;
    if (e >= E) return;
    int s = src[e], d = dst[e];
    float rx = (sp[s * 3 + 0] - dp[d * 3 + 0]) * INV_R;
    float ry = (sp[s * 3 + 1] - dp[d * 3 + 1]) * INV_R;
    float rz = (sp[s * 3 + 2] - dp[d * 3 + 2]) * INV_R;
    float w[8]; int b;
    edge_geom(rx, ry, rz, w, &b);
#pragma unroll
    for (int j = 0; j < 8; j++) w8[(size_t)e * 8 + j] = w[j];
    base[e] = b;
}

// Weight prep: W[K, Cout] fp32 -> transposed bf16 hi/lo [Cout, K]
__global__ void wprep_kernel(const float* __restrict__ W, __nv_bfloat16* __restrict__ h,
                             __nv_bfloat16* __restrict__ l, int K, int Cout)
{
    int i = blockIdx.x * blockDim.x + threadIdx.x;
    if (i >= K * Cout) return;
    int k = i / Cout, c = i - k * Cout;
    float v = W[i];
    __nv_bfloat16 hh = __float2bfloat16(v);
    h[(size_t)c * K + k] = hh;
    l[(size_t)c * K + k] = __float2bfloat16(v - __bfloat162float(hh));
}

// ---------------------------------------------------------------------------
// Scatter v2: ONE WARP PER DESTINATION, no atomics.
// Each warp owns a private 64*CIN smem row; lanes own disjoint channel pairs,
// edges processed sequentially -> plain LDS/FFMA/STS RMW. 8 dsts per CTA.
// ---------------------------------------------------------------------------
template <int CIN>
__global__ void __launch_bounds__(256, 1) scatter2_kernel(
    const float* __restrict__ x,
    const int* __restrict__ rs, const int* __restrict__ src,
    const float* __restrict__ w8, const int* __restrict__ base, int n)
{
    extern __shared__ float Ts[];              // 8 rows of NKERN*CIN floats
    const int lane = threadIdx.x & 31;
    const int wrp  = threadIdx.x >> 5;
    float* row = Ts + (size_t)wrp * (NKERN * CIN);

    // zero own row (float4)
    float4* rz = (float4*)row;
#pragma unroll 4
    for (int i = lane; i < NKERN * CIN / 4; i += 32) rz[i] = make_float4(0.f, 0.f, 0.f, 0.f);
    __syncwarp();

    const int d = blockIdx.x * 8 + wrp;
    if (d < n) {
        const int e0 = rs[d], e1 = rs[d + 1];
        for (int e = e0; e < e1; e++) {
            int s = __ldg(&src[e]);
            int b = __ldg(&base[e]);
            float4 wa = *(const float4*)&w8[(size_t)e * 8];
            float4 wb = *(const float4*)&w8[(size_t)e * 8 + 4];
            float wv[8] = {wa.x, wa.y, wa.z, wa.w, wb.x, wb.y, wb.z, wb.w};
            if (CIN % 2 == 0) {
                const float2* xr = (const float2*)(x + (size_t)s * CIN);
                float2* rr = (float2*)row;
#pragma unroll
                for (int p = lane; p < CIN / 2; p += 32) {
                    float2 v = __ldg(&xr[p]);
#pragma unroll
                    for (int j = 0; j < 8; j++) {
                        int idx = (b + c_offs[j]) * (CIN / 2) + p;
                        float2 cur = rr[idx];
                        cur.x += wv[j] * v.x;
                        cur.y += wv[j] * v.y;
                        rr[idx] = cur;
                    }
                }
            } else {
                const float* xr = x + (size_t)s * CIN;
                for (int c = lane; c < CIN; c += 32) {
                    float v = __ldg(&xr[c]);
#pragma unroll
                    for (int j = 0; j < 8; j++)
                        row[(b + c_offs[j]) * CIN + c] += wv[j] * v;
                }
            }
        }
    }
    __syncwarp();
    if (d >= n) return;

    // writeout: split to bf16 hi/lo, 2 channels per store
    size_t off = (size_t)d * (NKERN * CIN);
    __nv_bfloat162* oh = (__nv_bfloat162*)(g_Ahi + off);
    __nv_bfloat162* ol = (__nv_bfloat162*)(g_Alo + off);
    const float2* rr = (const float2*)row;
#pragma unroll 4
    for (int i = lane; i < NKERN * CIN / 2; i += 32) {
        float2 v = rr[i];
        __nv_bfloat162 h2 = __floats2bfloat162_rn(v.x, v.y);
        float rx = v.x - __bfloat162float(h2.x);
        float ry = v.y - __bfloat162float(h2.y);
        oh[i] = h2;
        ol[i] = __floats2bfloat162_rn(rx, ry);
    }
}

// ---------------------------------------------------------------------------
// HMMA GEMM (mma.sync bf16 split precision):
//   C[m, coff+0..NT) += (Ahi+Alo)[m,:] @ (Whi+Wlo)^T     (3 passes, fp32 acc)
// ---------------------------------------------------------------------------
#define BUFSZ 49152u
#define GEMM_SMEM (2 * 49152 + 1024)

template <int NT>
__global__ void __launch_bounds__(256, 1) mma_gemm_kernel(
    const __nv_bfloat16* __restrict__ Ahi, const __nv_bfloat16* __restrict__ Alo,
    const __nv_bfloat16* __restrict__ Bhi, const __nv_bfloat16* __restrict__ Blo,
    float* __restrict__ C, int Ktot, int ldc, int coff)
{
    extern __shared__ char dsm[];
    uint32_t tiles = (smem_u32(dsm) + 1023u) & ~1023u;
    const int tid = threadIdx.x;
    const int wid = tid >> 5, lid = tid & 31;
    const int m0 = blockIdx.x * 128;
    const int CH = Ktot >> 6;

    float acc[NT / 8][4];
#pragma unroll
    for (int i = 0; i < NT / 8; i++)
#pragma unroll
        for (int j = 0; j < 4; j++) acc[i][j] = 0.f;

    auto load_chunk = [&](int c, int b) {
        uint32_t bb = tiles + (uint32_t)b * BUFSZ;
        size_t kbase = (size_t)c * 64;
        for (int i = tid; i < 1024; i += 256) {
            int r = i >> 3, c8 = i & 7;
            uint32_t sw = sw128((uint32_t)(r * 128 + c8 * 16));
            size_t g = (size_t)(m0 + r) * Ktot + kbase + (size_t)c8 * 8;
            cp16(bb + sw, Ahi + g);
            cp16(bb + 16384u + sw, Alo + g);
        }
        for (int i = tid; i < NT * 8; i += 256) {
            int r = i >> 3, c8 = i & 7;
            uint32_t sw = sw128((uint32_t)(r * 128 + c8 * 16));
            size_t g = (size_t)r * Ktot + kbase + (size_t)c8 * 8;
            cp16(bb + 32768u + sw, Bhi + g);
            cp16(bb + 32768u + (uint32_t)NT * 128u + sw, Blo + g);
        }
        cp_commit();
    };

    load_chunk(0, 0);
    for (int i = 0; i < CH; i++) {
        if (i + 1 < CH) { load_chunk(i + 1, (i + 1) & 1); cp_wait<1>(); }
        else            { cp_wait<0>(); }
        __syncthreads();

        uint32_t bb  = tiles + (uint32_t)(i & 1) * BUFSZ;
        uint32_t aHi = bb, aLo = bb + 16384u;
        uint32_t bHi = bb + 32768u, bLo = bb + 32768u + (uint32_t)NT * 128u;

#pragma unroll
        for (int ks = 0; ks < 4; ks++) {
            uint32_t a_hi[4], a_lo[4];
            {
                int r = wid * 16 + (lid & 15);
                int c8 = ks * 2 + (lid >> 4);
                uint32_t sw = sw128((uint32_t)(r * 128 + c8 * 16));
                ldm_x4(a_hi, aHi + sw);
                ldm_x4(a_lo, aLo + sw);
            }
#pragma unroll
            for (int nc2 = 0; nc2 < NT / 16; nc2++) {
                uint32_t bh[4], bl[4];
                int g2 = lid >> 3;
                int rb = nc2 * 16 + (g2 >> 1) * 8 + (lid & 7);
                int cb8 = ks * 2 + (g2 & 1);
                uint32_t sw = sw128((uint32_t)(rb * 128 + cb8 * 16));
                ldm_x4(bh, bHi + sw);
                ldm_x4(bl, bLo + sw);
                mma_bf16(acc[nc2 * 2],     a_hi, bh[0], bh[1]);
                mma_bf16(acc[nc2 * 2],     a_hi, bl[0], bl[1]);
                mma_bf16(acc[nc2 * 2],     a_lo, bh[0], bh[1]);
                mma_bf16(acc[nc2 * 2 + 1], a_hi, bh[2], bh[3]);
                mma_bf16(acc[nc2 * 2 + 1], a_hi, bl[2], bl[3]);
                mma_bf16(acc[nc2 * 2 + 1], a_lo, bh[2], bh[3]);
            }
        }
        __syncthreads();
    }

    int gr = lid >> 2;
    int gc = (lid & 3) * 2;
    int m = m0 + wid * 16 + gr;
#pragma unroll
    for (int nc = 0; nc < NT / 8; nc++) {
        int col = coff + nc * 8 + gc;
        C[(size_t)m * ldc + col]           += acc[nc][0];
        C[(size_t)m * ldc + col + 1]       += acc[nc][1];
        C[(size_t)(m + 8) * ldc + col]     += acc[nc][2];
        C[(size_t)(m + 8) * ldc + col + 1] += acc[nc][3];
    }
}

// ---------------------------------------------------------------------------
// Dense path / misc
// ---------------------------------------------------------------------------
__global__ void dense_kernel(const float* __restrict__ x, const float* __restrict__ W,
                             const float* __restrict__ b1, const float* __restrict__ b2,
                             const float* __restrict__ skip, float* __restrict__ out,
                             int n, int cin, int cout, int ldo, int ooff)
{
    int idx = blockIdx.x * blockDim.x + threadIdx.x;
    if (idx >= n * cout) return;
    int i = idx / cout, o = idx - i * cout;
    float s = b1[o];
    if (b2) s += b2[o];
    if (skip) s += skip[(size_t)i * cout + o];
    const float* xr = x + (size_t)i * cin;
    for (int k = 0; k < cin; k++) s += xr[k] * W[(size_t)k * cout + o];
    out[(size_t)i * ldo + ooff + o] = s;
}

__global__ void bias_init96_kernel(const float* __restrict__ b0o, const float* __restrict__ b0f, int n)
{
    int idx = blockIdx.x * blockDim.x + threadIdx.x;
    if (idx >= n * 64) return;
    int i = idx >> 6, c = idx & 63;
    g_h96[(size_t)i * 96 + c] = (c < 32) ? b0o[c] : b0f[c - 32];
}

__global__ void relu_inplace_kernel(float* __restrict__ p, int cnt)
{
    int i = blockIdx.x * blockDim.x + threadIdx.x;
    if (i < cnt) p[i] = fmaxf(p[i], 0.f);
}

__global__ void relu_copy_kernel(const float* __restrict__ s, float* __restrict__ d, int cnt)
{
    int i = blockIdx.x * blockDim.x + threadIdx.x;
    if (i < cnt) d[i] = fmaxf(s[i], 0.f);
}

// Layer 3 conv (Cout=3): reads split T = hi + lo. One warp per destination.
__global__ void conv3_kernel(const float* __restrict__ W, float* __restrict__ h3, int n)
{
    __shared__ float Ws[4096 * 3];
    for (int i = threadIdx.x; i < 4096 * 3; i += 256) Ws[i] = W[i];
    __syncthreads();
    int wrp = threadIdx.x >> 5, lane = threadIdx.x & 31;
    int d = blockIdx.x * 8 + wrp;
    if (d >= n) return;
    size_t off = (size_t)d * 4096;
    float a0 = 0.f, a1 = 0.f, a2 = 0.f;
    for (int k = lane; k < 4096; k += 32) {
        float tv = __bfloat162float(g_Ahi[off + k]) + __bfloat162float(g_Alo[off + k]);
        a0 += tv * Ws[k * 3 + 0];
        a1 += tv * Ws[k * 3 + 1];
        a2 += tv * Ws[k * 3 + 2];
    }
#pragma unroll
    for (int o = 16; o > 0; o >>= 1) {
        a0 += __shfl_down_sync(0xffffffffu, a0, o);
        a1 += __shfl_down_sync(0xffffffffu, a1, o);
        a2 += __shfl_down_sync(0xffffffffu, a2, o);
    }
    if (lane == 0) {
        h3[d * 3 + 0] += a0;
        h3[d * 3 + 1] += a1;
        h3[d * 3 + 2] += a2;
    }
}

__global__ void finalize_kernel(const float* __restrict__ pos, float* __restrict__ out, int n)
{
    int i = blockIdx.x * blockDim.x + threadIdx.x;
    if (i >= n) return;
#pragma unroll
    for (int c = 0; c < 3; c++) {
        float pn = g_pos2[i * 3 + c] + g_h3[i * 3 + c] * (1.f / 128.f);
        out[i * 6 + c] = pn;
        out[i * 6 + 3 + c] = (pn - pos[i * 3 + c]) * INV_DT;
    }
}

// ---------------------------------------------------------------------------
// Host launcher
// ---------------------------------------------------------------------------
static void* symaddr(const void* sym)
{
    void* p = nullptr;
    cudaGetSymbolAddress(&p, sym);
    return p;
}

extern "C" void kernel_launch(void* const* d_in, const int* in_sizes, int n_in,
                              void* d_out, int out_size)
{
    const float* pos      = (const float*)d_in[0];
    const float* vel      = (const float*)d_in[1];
    const float* box      = (const float*)d_in[2];
    const float* box_fts  = (const float*)d_in[3];
    const int*   ff_src   = (const int*)d_in[4];
    const int*   ff_dst   = (const int*)d_in[5];
    const int*   bf_src   = (const int*)d_in[6];
    const int*   bf_dst   = (const int*)d_in[7];
    const float* W0f = (const float*)d_in[8],  *b0f = (const float*)d_in[9];
    const float* W0o = (const float*)d_in[10], *b0o = (const float*)d_in[11];
    const float* Wd0 = (const float*)d_in[12], *bd0 = (const float*)d_in[13];
    const float* Wc1 = (const float*)d_in[14], *bc1 = (const float*)d_in[15];
    const float* Wd1 = (const float*)d_in[16], *bd1 = (const float*)d_in[17];
    const float* Wc2 = (const float*)d_in[18], *bc2 = (const float*)d_in[19];
    const float* Wd2 = (const float*)d_in[20], *bd2 = (const float*)d_in[21];
    const float* Wc3 = (const float*)d_in[22], *bc3 = (const float*)d_in[23];
    const float* Wd3 = (const float*)d_in[24], *bd3 = (const float*)d_in[25];

    int n   = in_sizes[0] / 3;
    int Eff = in_sizes[4]; if (Eff > MAXE)  Eff = MAXE;
    int Ebf = in_sizes[6]; if (Ebf > MAXBE) Ebf = MAXBE;

    __nv_bfloat16* pAhi = (__nv_bfloat16*)symaddr(g_Ahi);
    __nv_bfloat16* pAlo = (__nv_bfloat16*)symaddr(g_Alo);
    __nv_bfloat16* pWh  = (__nv_bfloat16*)symaddr(g_Wh);
    __nv_bfloat16* pWl  = (__nv_bfloat16*)symaddr(g_Wl);
    float* pW8   = (float*)symaddr(g_w8);
    int*   pB    = (int*)symaddr(g_base);
    float* pW8b  = (float*)symaddr(g_w8b);
    int*   pBb   = (int*)symaddr(g_baseb);
    int*   pRsF  = (int*)symaddr(g_rs_ff);
    int*   pRsB  = (int*)symaddr(g_rs_bf);
    float* pPos2 = (float*)symaddr(g_pos2);
    float* pFeat = (float*)symaddr(g_feats);
    float* pH96  = (float*)symaddr(g_h96);
    float* pH1   = (float*)symaddr(g_h1);
    float* pH2   = (float*)symaddr(g_h2);
    float* pX64  = (float*)symaddr(g_x64);
    float* pH3   = (float*)symaddr(g_h3);

    cudaFuncSetAttribute(mma_gemm_kernel<32>, cudaFuncAttributeMaxDynamicSharedMemorySize, GEMM_SMEM);
    cudaFuncSetAttribute(mma_gemm_kernel<64>, cudaFuncAttributeMaxDynamicSharedMemorySize, GEMM_SMEM);
    cudaFuncSetAttribute(scatter2_kernel<96>, cudaFuncAttributeMaxDynamicSharedMemorySize, 8 * NKERN * 96 * 4);
    cudaFuncSetAttribute(scatter2_kernel<64>, cudaFuncAttributeMaxDynamicSharedMemorySize, 8 * NKERN * 64 * 4);
    cudaFuncSetAttribute(scatter2_kernel<4>,  cudaFuncAttributeMaxDynamicSharedMemorySize, 8 * NKERN * 4 * 4);
    cudaFuncSetAttribute(scatter2_kernel<3>,  cudaFuncAttributeMaxDynamicSharedMemorySize, 8 * NKERN * 3 * 4);

    const int TB = 256;
    const int SGRID = (n + 7) / 8;   // 2048

    // 1. integrate + features
    prep_kernel<<<(n + TB - 1) / TB, TB>>>(pos, vel, n);

    // 2. CSR row offsets
    fill_int_kernel<<<(n + 1 + TB - 1) / TB, TB>>>(pRsF, Eff, n + 1);
    fill_int_kernel<<<(n + 1 + TB - 1) / TB, TB>>>(pRsB, Ebf, n + 1);
    if (Eff > 0) rowstart_kernel<<<(Eff + TB - 1) / TB, TB>>>(ff_dst, Eff, pRsF);
    if (Ebf > 0) rowstart_kernel<<<(Ebf + TB - 1) / TB, TB>>>(bf_dst, Ebf, pRsB);

    // 3. edge geometry tables
    if (Eff > 0) geom_kernel<<<(Eff + TB - 1) / TB, TB>>>(pPos2, pPos2, ff_src, ff_dst, Eff, pW8, pB);
    if (Ebf > 0) geom_kernel<<<(Ebf + TB - 1) / TB, TB>>>(box, pPos2, bf_src, bf_dst, Ebf, pW8b, pBb);

    // 3b. split + transpose conv weights to bf16 hi/lo
    wprep_kernel<<<(6144 * 64 + TB - 1) / TB, TB>>>(Wc1, pWh + OFF_WC1, pWl + OFF_WC1, 6144, 64);
    wprep_kernel<<<(4096 * 64 + TB - 1) / TB, TB>>>(Wc2, pWh + OFF_WC2, pWl + OFF_WC2, 4096, 64);
    wprep_kernel<<<(256 * 32 + TB - 1) / TB, TB>>>(W0f, pWh + OFF_W0F, pWl + OFF_W0F, 256, 32);
    wprep_kernel<<<(192 * 32 + TB - 1) / TB, TB>>>(W0o, pWh + OFF_W0O, pWl + OFF_W0O, 192, 32);

    // 4. layer 0: h = [c0o | c0f | d0]
    bias_init96_kernel<<<(n * 64 + TB - 1) / TB, TB>>>(b0o, b0f, n);
    dense_kernel<<<(n * 32 + TB - 1) / TB, TB>>>(pFeat, Wd0, bd0, nullptr, nullptr, pH96, n, 4, 32, 96, 64);
    scatter2_kernel<4><<<SGRID, TB, 8 * NKERN * 4 * 4>>>(pFeat, pRsF, ff_src, pW8, pB, n);
    mma_gemm_kernel<32><<<n / 128, TB, GEMM_SMEM>>>(pAhi, pAlo, pWh + OFF_W0F, pWl + OFF_W0F, pH96, 256, 96, 32);
    scatter2_kernel<3><<<SGRID, TB, 8 * NKERN * 3 * 4>>>(box_fts, pRsB, bf_src, pW8b, pBb, n);
    mma_gemm_kernel<32><<<n / 128, TB, GEMM_SMEM>>>(pAhi, pAlo, pWh + OFF_W0O, pWl + OFF_W0O, pH96, 192, 96, 0);
    relu_inplace_kernel<<<(n * 96 + TB - 1) / TB, TB>>>(pH96, n * 96);

    // 5. layer 1
    dense_kernel<<<(n * 64 + TB - 1) / TB, TB>>>(pH96, Wd1, bd1, bc1, nullptr, pH1, n, 96, 64, 64, 0);
    scatter2_kernel<96><<<SGRID, TB, 8 * NKERN * 96 * 4>>>(pH96, pRsF, ff_src, pW8, pB, n);
    mma_gemm_kernel<64><<<n / 128, TB, GEMM_SMEM>>>(pAhi, pAlo, pWh + OFF_WC1, pWl + OFF_WC1, pH1, 6144, 64, 0);
    relu_copy_kernel<<<(n * 64 + TB - 1) / TB, TB>>>(pH1, pX64, n * 64);

    // 6. layer 2
    dense_kernel<<<(n * 64 + TB - 1) / TB, TB>>>(pX64, Wd2, bd2, bc2, pH1, pH2, n, 64, 64, 64, 0);
    scatter2_kernel<64><<<SGRID, TB, 8 * NKERN * 64 * 4>>>(pX64, pRsF, ff_src, pW8, pB, n);
    mma_gemm_kernel<64><<<n / 128, TB, GEMM_SMEM>>>(pAhi, pAlo, pWh + OFF_WC2, pWl + OFF_WC2, pH2, 4096, 64, 0);
    relu_inplace_kernel<<<(n * 64 + TB - 1) / TB, TB>>>(pH2, n * 64);

    // 7. layer 3
    dense_kernel<<<(n * 3 + TB - 1) / TB, TB>>>(pH2, Wd3, bd3, bc3, nullptr, pH3, n, 64, 3, 3, 0);
    scatter2_kernel<64><<<SGRID, TB, 8 * NKERN * 64 * 4>>>(pH2, pRsF, ff_src, pW8, pB, n);
    conv3_kernel<<<(n + 7) / 8, TB>>>(Wc3, pH3, n);

    // 8. integrate output
    finalize_kernel<<<(n + TB - 1) / TB, TB>>>(pos, (float*)d_out, n);
    (void)n_in; (void)out_size;
}

// round 7
// speedup vs baseline: 1.5534x; 1.5534x over previous
#include <cuda_runtime.h>
#include <cuda_bf16.h>
#include <math.h>
#include <stdint.h>

// ---------------------------------------------------------------------------
// Problem constants (fixed instance)
// ---------------------------------------------------------------------------
#define N_P    16384
#define NKERN  64
#define MAXE   3000000
#define MAXBE  1000000
#define RADIUS_F 0.1125f
#define INV_R   (1.0f / RADIUS_F)
#define DT_F    0.02f
#define INV_DT  50.0f
#define GRAV_Y  (-9.81f)
#define FOUR_OVER_PI_F 1.2732395447351628f

// ---------------------------------------------------------------------------
// Static device scratch
// ---------------------------------------------------------------------------
__device__ __align__(256) __nv_bfloat16 g_A[(size_t)N_P * 6144];   // patch tensor, bf16
// packed bf16 weights (transposed to [Cout, K]): Wc1 | Wc2 | W0f | W0o
#define OFF_WC1 0
#define OFF_WC2 393216
#define OFF_W0F 655360
#define OFF_W0O 663552
#define W_TOTAL 669696
__device__ __align__(256) __nv_bfloat16 g_Wh[W_TOTAL];

__device__ float g_w8[(size_t)MAXE * 8];
__device__ int   g_base[MAXE];
__device__ float g_w8b[(size_t)MAXBE * 8];
__device__ int   g_baseb[MAXBE];
__device__ int   g_rs_ff[N_P + 1];
__device__ int   g_rs_bf[N_P + 1];
__device__ float g_pos2[N_P * 3];
__device__ float g_feats[N_P * 4];
__device__ float g_h96[N_P * 96];
__device__ float g_h1[N_P * 64];
__device__ float g_h2[N_P * 64];
__device__ float g_x64[N_P * 64];
__device__ float g_h3[N_P * 3];

// ---------------------------------------------------------------------------
// PTX helpers (cp.async / ldmatrix / mma.sync — all valid on compute_103)
// ---------------------------------------------------------------------------
__device__ __forceinline__ uint32_t smem_u32(const void* p) {
    uint32_t a;
    asm("{ .reg .u64 t; cvta.to.shared.u64 t, %1; cvt.u32.u64 %0, t; }" : "=r"(a) : "l"(p));
    return a;
}

__device__ __forceinline__ void cp16(uint32_t dst, const void* src) {
    asm volatile("cp.async.cg.shared.global [%0], [%1], 16;" :: "r"(dst), "l"(src));
}
__device__ __forceinline__ void cp_commit() { asm volatile("cp.async.commit_group;"); }
template <int N>
__device__ __forceinline__ void cp_wait() { asm volatile("cp.async.wait_group %0;" :: "n"(N)); }

__device__ __forceinline__ void ldm_x4(uint32_t* r, uint32_t addr) {
    asm volatile("ldmatrix.sync.aligned.m8n8.x4.shared.b16 {%0,%1,%2,%3}, [%4];"
                 : "=r"(r[0]), "=r"(r[1]), "=r"(r[2]), "=r"(r[3]) : "r"(addr));
}

__device__ __forceinline__ void mma_bf16(float* d, const uint32_t* a, uint32_t b0, uint32_t b1) {
    asm volatile(
        "mma.sync.aligned.m16n8k16.row.col.f32.bf16.bf16.f32 "
        "{%0,%1,%2,%3}, {%4,%5,%6,%7}, {%8,%9}, {%0,%1,%2,%3};"
        : "+f"(d[0]), "+f"(d[1]), "+f"(d[2]), "+f"(d[3])
        : "r"(a[0]), "r"(a[1]), "r"(a[2]), "r"(a[3]), "r"(b0), "r"(b1));
}

__device__ __forceinline__ uint32_t sw128(uint32_t off) {
    return off ^ ((off >> 3) & 0x70u);
}

// ---------------------------------------------------------------------------
// Geometry (mirrors JAX reference)
// ---------------------------------------------------------------------------
__device__ __forceinline__ float signf(float x) {
    return (x > 0.f) ? 1.f : ((x < 0.f) ? -1.f : 0.f);
}

__device__ __forceinline__ void edge_geom(float x, float y, float z,
                                          float* __restrict__ w8, int* __restrict__ basep)
{
    float r2 = x * x + y * y + z * z;
    float win = 1.f - r2;
    win = win * win * win;
    win = fminf(fmaxf(win, 0.f), 1.f);

    float norm = sqrtf(r2 + 1e-24f);
    float xy_sq = x * x + y * y;
    bool zero = r2 < 1e-12f;
    bool cone = 1.25f * z * z > xy_sq;
    float s_cone = sqrtf(3.f * norm / (norm + fabsf(z) + 1e-12f));
    float s_side = norm / sqrtf(xy_sq + 1e-24f);
    float xc = zero ? 0.f : (cone ? x * s_cone : x * s_side);
    float yc = zero ? 0.f : (cone ? y * s_cone : y * s_side);
    float zc = zero ? 0.f : (cone ? signf(z) * norm : 1.5f * z);

    float nxy_sq = xc * xc + yc * yc;
    float nxy = sqrtf(nxy_sq + 1e-24f);
    bool zero_xy = nxy_sq < 1e-12f;
    bool xbig = fabsf(xc) > fabsf(yc);
    float dx_ = (fabsf(xc) > 1e-12f) ? xc : 1.f;
    float dy_ = (fabsf(yc) > 1e-12f) ? yc : 1.f;
    float tx = signf(xc) * nxy;
    float ty = signf(yc) * nxy;
    float xq = zero_xy ? 0.f : (xbig ? tx : ty * FOUR_OVER_PI_F * atanf(xc / dy_));
    float yq = zero_xy ? 0.f : (xbig ? tx * FOUR_OVER_PI_F * atanf(yc / dx_) : ty);

    float gx = (xq + 1.f) * 1.5f;
    float gy = (yq + 1.f) * 1.5f;
    float gz = (zc + 1.f) * 1.5f;
    float g0x = fminf(fmaxf(floorf(gx), 0.f), 2.f);
    float g0y = fminf(fmaxf(floorf(gy), 0.f), 2.f);
    float g0z = fminf(fmaxf(floorf(gz), 0.f), 2.f);
    float fx = gx - g0x, fy = gy - g0y, fz = gz - g0z;
    int base = (int)g0z * 16 + (int)g0y * 4 + (int)g0x;
    float ax = 1.f - fx, ay = 1.f - fy, az = 1.f - fz;

    w8[0] = az * ay * ax * win;
    w8[1] = az * ay * fx * win;
    w8[2] = az * fy * ax * win;
    w8[3] = az * fy * fx * win;
    w8[4] = fz * ay * ax * win;
    w8[5] = fz * ay * fx * win;
    w8[6] = fz * fy * ax * win;
    w8[7] = fz * fy * fx * win;
    *basep = base;
}

__constant__ int c_offs[8] = {0, 1, 4, 5, 16, 17, 20, 21};

// ---------------------------------------------------------------------------
// Small kernels
// ---------------------------------------------------------------------------
__global__ void prep_kernel(const float* __restrict__ pos, const float* __restrict__ vel, int n)
{
    int i = blockIdx.x * blockDim.x + threadIdx.x;
    if (i >= n) return;
    float vx = vel[i * 3 + 0], vy = vel[i * 3 + 1], vz = vel[i * 3 + 2];
    float v2x = vx, v2y = vy + DT_F * GRAV_Y, v2z = vz;
    g_pos2[i * 3 + 0] = pos[i * 3 + 0] + DT_F * 0.5f * (v2x + vx);
    g_pos2[i * 3 + 1] = pos[i * 3 + 1] + DT_F * 0.5f * (v2y + vy);
    g_pos2[i * 3 + 2] = pos[i * 3 + 2] + DT_F * 0.5f * (v2z + vz);
    g_feats[i * 4 + 0] = 1.f;
    g_feats[i * 4 + 1] = v2x;
    g_feats[i * 4 + 2] = v2y;
    g_feats[i * 4 + 3] = v2z;
}

__global__ void fill_int_kernel(int* __restrict__ p, int v, int cnt)
{
    int i = blockIdx.x * blockDim.x + threadIdx.x;
    if (i < cnt) p[i] = v;
}

__global__ void rowstart_kernel(const int* __restrict__ dst, int E, int* __restrict__ rs)
{
    int e = blockIdx.x * blockDim.x + threadIdx.x;
    if (e >= E) return;
    int d = dst[e];
    int p = (e == 0) ? -1 : dst[e - 1];
    for (int dd = p + 1; dd <= d; dd++) rs[dd] = e;
}

__global__ void geom_kernel(const float* __restrict__ sp, const float* __restrict__ dp,
                            const int* __restrict__ src, const int* __restrict__ dst, int E,
                            float* __restrict__ w8, int* __restrict__ base)
{
    int e = blockIdx.x * blockDim.x + threadIdx.x;
    if (e >= E) return;
    int s = src[e], d = dst[e];
    float rx = (sp[s * 3 + 0] - dp[d * 3 + 0]) * INV_R;
    float ry = (sp[s * 3 + 1] - dp[d * 3 + 1]) * INV_R;
    float rz = (sp[s * 3 + 2] - dp[d * 3 + 2]) * INV_R;
    float w[8]; int b;
    edge_geom(rx, ry, rz, w, &b);
#pragma unroll
    for (int j = 0; j < 8; j++) w8[(size_t)e * 8 + j] = w[j];
    base[e] = b;
}

// Weight prep: W[K, Cout] fp32 -> transposed bf16 [Cout, K]
__global__ void wprep_kernel(const float* __restrict__ W, __nv_bfloat16* __restrict__ h,
                             int K, int Cout)
{
    int i = blockIdx.x * blockDim.x + threadIdx.x;
    if (i >= K * Cout) return;
    int k = i / Cout, c = i - k * Cout;
    h[(size_t)c * K + k] = __float2bfloat16(W[i]);
}

// ---------------------------------------------------------------------------
// Scatter (R3 atomic form — fire-and-forget shared atomics, pipelined):
// one block per destination, shared fp32 T row, bf16 writeout.
// ---------------------------------------------------------------------------
template <int CIN>
__global__ void scatter_kernel(const float* __restrict__ x,
                               const int* __restrict__ rs, const int* __restrict__ src,
                               const float* __restrict__ w8, const int* __restrict__ base)
{
    __shared__ float Ts[NKERN * CIN];
    int d = blockIdx.x;
    int t = threadIdx.x;
    for (int i = t; i < NKERN * CIN; i += 256) Ts[i] = 0.f;
    __syncthreads();
    int e0 = rs[d], e1 = rs[d + 1];
    int lane = t & 31, wrp = t >> 5;
    for (int e = e0 + wrp; e < e1; e += 8) {
        int s = src[e];
        int b = base[e];
        float4 wa = *(const float4*)&w8[(size_t)e * 8];
        float4 wb = *(const float4*)&w8[(size_t)e * 8 + 4];
        float wv[8] = {wa.x, wa.y, wa.z, wa.w, wb.x, wb.y, wb.z, wb.w};
#pragma unroll
        for (int c = lane; c < CIN; c += 32) {
            float v = x[(size_t)s * CIN + c];
#pragma unroll
            for (int j = 0; j < 8; j++)
                atomicAdd(&Ts[(b + c_offs[j]) * CIN + c], wv[j] * v);
        }
    }
    __syncthreads();
    size_t off = (size_t)d * (NKERN * CIN);
    if (CIN % 2 == 0) {
        __nv_bfloat162* oh = (__nv_bfloat162*)(g_A + off);
        const float2* rr = (const float2*)Ts;
        for (int i = t; i < NKERN * CIN / 2; i += 256) {
            float2 v = rr[i];
            oh[i] = __floats2bfloat162_rn(v.x, v.y);
        }
    } else {
        for (int i = t; i < NKERN * CIN; i += 256)
            g_A[off + i] = __float2bfloat16(Ts[i]);
    }
}

// ---------------------------------------------------------------------------
// HMMA GEMM (single-pass bf16): C[m, coff+0..NT) += A[m,:] @ W^T, fp32 acc.
// A: [16384, Ktot] bf16 row-major. B: [NT, Ktot] bf16 row-major.
// CTA: 256 thr (8 warps), tile 128 x NT, K-chunks of 64, cp.async dbl-buffer.
// ---------------------------------------------------------------------------
template <int NT>
__global__ void __launch_bounds__(256, 1) mma_gemm_kernel(
    const __nv_bfloat16* __restrict__ A,
    const __nv_bfloat16* __restrict__ B,
    float* __restrict__ C, int Ktot, int ldc, int coff)
{
    constexpr uint32_t BUF = 16384u + (uint32_t)NT * 128u;
    extern __shared__ char dsm[];
    uint32_t tiles = (smem_u32(dsm) + 1023u) & ~1023u;
    const int tid = threadIdx.x;
    const int wid = tid >> 5, lid = tid & 31;
    const int m0 = blockIdx.x * 128;
    const int CH = Ktot >> 6;

    float acc[NT / 8][4];
#pragma unroll
    for (int i = 0; i < NT / 8; i++)
#pragma unroll
        for (int j = 0; j < 4; j++) acc[i][j] = 0.f;

    auto load_chunk = [&](int c, int b) {
        uint32_t bb = tiles + (uint32_t)b * BUF;
        size_t kbase = (size_t)c * 64;
        for (int i = tid; i < 1024; i += 256) {
            int r = i >> 3, c8 = i & 7;
            uint32_t sw = sw128((uint32_t)(r * 128 + c8 * 16));
            size_t g = (size_t)(m0 + r) * Ktot + kbase + (size_t)c8 * 8;
            cp16(bb + sw, A + g);
        }
        for (int i = tid; i < NT * 8; i += 256) {
            int r = i >> 3, c8 = i & 7;
            uint32_t sw = sw128((uint32_t)(r * 128 + c8 * 16));
            size_t g = (size_t)r * Ktot + kbase + (size_t)c8 * 8;
            cp16(bb + 16384u + sw, B + g);
        }
        cp_commit();
    };

    load_chunk(0, 0);
    for (int i = 0; i < CH; i++) {
        if (i + 1 < CH) { load_chunk(i + 1, (i + 1) & 1); cp_wait<1>(); }
        else            { cp_wait<0>(); }
        __syncthreads();

        uint32_t bb = tiles + (uint32_t)(i & 1) * BUF;
        uint32_t aB = bb, bB = bb + 16384u;

#pragma unroll
        for (int ks = 0; ks < 4; ks++) {
            uint32_t a[4];
            {
                int r = wid * 16 + (lid & 15);
                int c8 = ks * 2 + (lid >> 4);
                uint32_t sw = sw128((uint32_t)(r * 128 + c8 * 16));
                ldm_x4(a, aB + sw);
            }
#pragma unroll
            for (int nc2 = 0; nc2 < NT / 16; nc2++) {
                uint32_t bh[4];
                int g2 = lid >> 3;
                int rb = nc2 * 16 + (g2 >> 1) * 8 + (lid & 7);
                int cb8 = ks * 2 + (g2 & 1);
                uint32_t sw = sw128((uint32_t)(rb * 128 + cb8 * 16));
                ldm_x4(bh, bB + sw);
                mma_bf16(acc[nc2 * 2],     a, bh[0], bh[1]);
                mma_bf16(acc[nc2 * 2 + 1], a, bh[2], bh[3]);
            }
        }
        __syncthreads();
    }

    int gr = lid >> 2;
    int gc = (lid & 3) * 2;
    int m = m0 + wid * 16 + gr;
#pragma unroll
    for (int nc = 0; nc < NT / 8; nc++) {
        int col = coff + nc * 8 + gc;
        C[(size_t)m * ldc + col]           += acc[nc][0];
        C[(size_t)m * ldc + col + 1]       += acc[nc][1];
        C[(size_t)(m + 8) * ldc + col]     += acc[nc][2];
        C[(size_t)(m + 8) * ldc + col + 1] += acc[nc][3];
    }
}

// ---------------------------------------------------------------------------
// Dense path / misc
// ---------------------------------------------------------------------------
__global__ void dense_kernel(const float* __restrict__ x, const float* __restrict__ W,
                             const float* __restrict__ b1, const float* __restrict__ b2,
                             const float* __restrict__ skip, float* __restrict__ out,
                             int n, int cin, int cout, int ldo, int ooff)
{
    int idx = blockIdx.x * blockDim.x + threadIdx.x;
    if (idx >= n * cout) return;
    int i = idx / cout, o = idx - i * cout;
    float s = b1[o];
    if (b2) s += b2[o];
    if (skip) s += skip[(size_t)i * cout + o];
    const float* xr = x + (size_t)i * cin;
    for (int k = 0; k < cin; k++) s += xr[k] * W[(size_t)k * cout + o];
    out[(size_t)i * ldo + ooff + o] = s;
}

__global__ void bias_init96_kernel(const float* __restrict__ b0o, const float* __restrict__ b0f, int n)
{
    int idx = blockIdx.x * blockDim.x + threadIdx.x;
    if (idx >= n * 64) return;
    int i = idx >> 6, c = idx & 63;
    g_h96[(size_t)i * 96 + c] = (c < 32) ? b0o[c] : b0f[c - 32];
}

__global__ void relu_inplace_kernel(float* __restrict__ p, int cnt)
{
    int i = blockIdx.x * blockDim.x + threadIdx.x;
    if (i < cnt) p[i] = fmaxf(p[i], 0.f);
}

__global__ void relu_copy_kernel(const float* __restrict__ s, float* __restrict__ d, int cnt)
{
    int i = blockIdx.x * blockDim.x + threadIdx.x;
    if (i < cnt) d[i] = fmaxf(s[i], 0.f);
}

// Layer 3 conv (Cout=3): T in bf16. One warp per destination.
__global__ void conv3_kernel(const float* __restrict__ W, float* __restrict__ h3, int n)
{
    __shared__ float Ws[4096 * 3];
    for (int i = threadIdx.x; i < 4096 * 3; i += 256) Ws[i] = W[i];
    __syncthreads();
    int wrp = threadIdx.x >> 5, lane = threadIdx.x & 31;
    int d = blockIdx.x * 8 + wrp;
    if (d >= n) return;
    size_t off = (size_t)d * 4096;
    const __nv_bfloat162* Tr = (const __nv_bfloat162*)(g_A + off);
    float a0 = 0.f, a1 = 0.f, a2 = 0.f;
    for (int p = lane; p < 2048; p += 32) {
        __nv_bfloat162 tv2 = Tr[p];
        float t0 = __bfloat162float(tv2.x);
        float t1 = __bfloat162float(tv2.y);
        int k = p * 2;
        a0 += t0 * Ws[k * 3 + 0] + t1 * Ws[k * 3 + 3];
        a1 += t0 * Ws[k * 3 + 1] + t1 * Ws[k * 3 + 4];
        a2 += t0 * Ws[k * 3 + 2] + t1 * Ws[k * 3 + 5];
    }
#pragma unroll
    for (int o = 16; o > 0; o >>= 1) {
        a0 += __shfl_down_sync(0xffffffffu, a0, o);
        a1 += __shfl_down_sync(0xffffffffu, a1, o);
        a2 += __shfl_down_sync(0xffffffffu, a2, o);
    }
    if (lane == 0) {
        h3[d * 3 + 0] += a0;
        h3[d * 3 + 1] += a1;
        h3[d * 3 + 2] += a2;
    }
}

__global__ void finalize_kernel(const float* __restrict__ pos, float* __restrict__ out, int n)
{
    int i = blockIdx.x * blockDim.x + threadIdx.x;
    if (i >= n) return;
#pragma unroll
    for (int c = 0; c < 3; c++) {
        float pn = g_pos2[i * 3 + c] + g_h3[i * 3 + c] * (1.f / 128.f);
        out[i * 6 + c] = pn;
        out[i * 6 + 3 + c] = (pn - pos[i * 3 + c]) * INV_DT;
    }
}

// ---------------------------------------------------------------------------
// Host launcher
// ---------------------------------------------------------------------------
static void* symaddr(const void* sym)
{
    void* p = nullptr;
    cudaGetSymbolAddress(&p, sym);
    return p;
}

extern "C" void kernel_launch(void* const* d_in, const int* in_sizes, int n_in,
                              void* d_out, int out_size)
{
    const float* pos      = (const float*)d_in[0];
    const float* vel      = (const float*)d_in[1];
    const float* box      = (const float*)d_in[2];
    const float* box_fts  = (const float*)d_in[3];
    const int*   ff_src   = (const int*)d_in[4];
    const int*   ff_dst   = (const int*)d_in[5];
    const int*   bf_src   = (const int*)d_in[6];
    const int*   bf_dst   = (const int*)d_in[7];
    const float* W0f = (const float*)d_in[8],  *b0f = (const float*)d_in[9];
    const float* W0o = (const float*)d_in[10], *b0o = (const float*)d_in[11];
    const float* Wd0 = (const float*)d_in[12], *bd0 = (const float*)d_in[13];
    const float* Wc1 = (const float*)d_in[14], *bc1 = (const float*)d_in[15];
    const float* Wd1 = (const float*)d_in[16], *bd1 = (const float*)d_in[17];
    const float* Wc2 = (const float*)d_in[18], *bc2 = (const float*)d_in[19];
    const float* Wd2 = (const float*)d_in[20], *bd2 = (const float*)d_in[21];
    const float* Wc3 = (const float*)d_in[22], *bc3 = (const float*)d_in[23];
    const float* Wd3 = (const float*)d_in[24], *bd3 = (const float*)d_in[25];

    int n   = in_sizes[0] / 3;
    int Eff = in_sizes[4]; if (Eff > MAXE)  Eff = MAXE;
    int Ebf = in_sizes[6]; if (Ebf > MAXBE) Ebf = MAXBE;

    __nv_bfloat16* pA  = (__nv_bfloat16*)symaddr(g_A);
    __nv_bfloat16* pWh = (__nv_bfloat16*)symaddr(g_Wh);
    float* pW8   = (float*)symaddr(g_w8);
    int*   pB    = (int*)symaddr(g_base);
    float* pW8b  = (float*)symaddr(g_w8b);
    int*   pBb   = (int*)symaddr(g_baseb);
    int*   pRsF  = (int*)symaddr(g_rs_ff);
    int*   pRsB  = (int*)symaddr(g_rs_bf);
    float* pPos2 = (float*)symaddr(g_pos2);
    float* pFeat = (float*)symaddr(g_feats);
    float* pH96  = (float*)symaddr(g_h96);
    float* pH1   = (float*)symaddr(g_h1);
    float* pH2   = (float*)symaddr(g_h2);
    float* pX64  = (float*)symaddr(g_x64);
    float* pH3   = (float*)symaddr(g_h3);

    // dynamic smem: double buffer + 1KB align slack
    const int SM32 = 2 * (16384 + 32 * 128) + 1024;   // 41984
    const int SM64 = 2 * (16384 + 64 * 128) + 1024;   // 50176
    cudaFuncSetAttribute(mma_gemm_kernel<32>, cudaFuncAttributeMaxDynamicSharedMemorySize, SM32);
    cudaFuncSetAttribute(mma_gemm_kernel<64>, cudaFuncAttributeMaxDynamicSharedMemorySize, SM64);

    const int TB = 256;
    // 1. integrate + features
    prep_kernel<<<(n + TB - 1) / TB, TB>>>(pos, vel, n);

    // 2. CSR row offsets
    fill_int_kernel<<<(n + 1 + TB - 1) / TB, TB>>>(pRsF, Eff, n + 1);
    fill_int_kernel<<<(n + 1 + TB - 1) / TB, TB>>>(pRsB, Ebf, n + 1);
    if (Eff > 0) rowstart_kernel<<<(Eff + TB - 1) / TB, TB>>>(ff_dst, Eff, pRsF);
    if (Ebf > 0) rowstart_kernel<<<(Ebf + TB - 1) / TB, TB>>>(bf_dst, Ebf, pRsB);

    // 3. edge geometry tables
    if (Eff > 0) geom_kernel<<<(Eff + TB - 1) / TB, TB>>>(pPos2, pPos2, ff_src, ff_dst, Eff, pW8, pB);
    if (Ebf > 0) geom_kernel<<<(Ebf + TB - 1) / TB, TB>>>(box, pPos2, bf_src, bf_dst, Ebf, pW8b, pBb);

    // 3b. transpose conv weights to bf16 [Cout, K]
    wprep_kernel<<<(6144 * 64 + TB - 1) / TB, TB>>>(Wc1, pWh + OFF_WC1, 6144, 64);
    wprep_kernel<<<(4096 * 64 + TB - 1) / TB, TB>>>(Wc2, pWh + OFF_WC2, 4096, 64);
    wprep_kernel<<<(256 * 32 + TB - 1) / TB, TB>>>(W0f, pWh + OFF_W0F, 256, 32);
    wprep_kernel<<<(192 * 32 + TB - 1) / TB, TB>>>(W0o, pWh + OFF_W0O, 192, 32);

    // 4. layer 0: h = [c0o | c0f | d0]
    bias_init96_kernel<<<(n * 64 + TB - 1) / TB, TB>>>(b0o, b0f, n);
    dense_kernel<<<(n * 32 + TB - 1) / TB, TB>>>(pFeat, Wd0, bd0, nullptr, nullptr, pH96, n, 4, 32, 96, 64);
    scatter_kernel<4><<<n, TB>>>(pFeat, pRsF, ff_src, pW8, pB);
    mma_gemm_kernel<32><<<n / 128, TB, SM32>>>(pA, pWh + OFF_W0F, pH96, 256, 96, 32);
    scatter_kernel<3><<<n, TB>>>(box_fts, pRsB, bf_src, pW8b, pBb);
    mma_gemm_kernel<32><<<n / 128, TB, SM32>>>(pA, pWh + OFF_W0O, pH96, 192, 96, 0);
    relu_inplace_kernel<<<(n * 96 + TB - 1) / TB, TB>>>(pH96, n * 96);

    // 5. layer 1
    dense_kernel<<<(n * 64 + TB - 1) / TB, TB>>>(pH96, Wd1, bd1, bc1, nullptr, pH1, n, 96, 64, 64, 0);
    scatter_kernel<96><<<n, TB>>>(pH96, pRsF, ff_src, pW8, pB);
    mma_gemm_kernel<64><<<n / 128, TB, SM64>>>(pA, pWh + OFF_WC1, pH1, 6144, 64, 0);
    relu_copy_kernel<<<(n * 64 + TB - 1) / TB, TB>>>(pH1, pX64, n * 64);

    // 6. layer 2
    dense_kernel<<<(n * 64 + TB - 1) / TB, TB>>>(pX64, Wd2, bd2, bc2, pH1, pH2, n, 64, 64, 64, 0);
    scatter_kernel<64><<<n, TB>>>(pX64, pRsF, ff_src, pW8, pB);
    mma_gemm_kernel<64><<<n / 128, TB, SM64>>>(pA, pWh + OFF_WC2, pH2, 4096, 64, 0);
    relu_inplace_kernel<<<(n * 64 + TB - 1) / TB, TB>>>(pH2, n * 64);

    // 7. layer 3
    dense_kernel<<<(n * 3 + TB - 1) / TB, TB>>>(pH2, Wd3, bd3, bc3, nullptr, pH3, n, 64, 3, 3, 0);
    scatter_kernel<64><<<n, TB>>>(pH2, pRsF, ff_src, pW8, pB);
    conv3_kernel<<<(n + 7) / 8, TB>>>(Wc3, pH3, n);

    // 8. integrate output
    finalize_kernel<<<(n + TB - 1) / TB, TB>>>(pos, (float*)d_out, n);
    (void)n_in; (void)out_size;
}